// round 1
// baseline (speedup 1.0000x reference)
#include <cuda_runtime.h>
#include <cuda_bf16.h>

#define BB 32
#define HH 4
#define SS 4096
#define MM 128

// Scratch (allocation-free rule: __device__ globals)
__device__ float g_w[BB * HH * SS];     // dots, then softmax weights in-place
__device__ float g_rmn[BB * SS];        // 1 / max(||mem_row||, eps)

// ---------------------------------------------------------------------------
// Kernel 1: per memory row s, compute 4 dot products with k[b,h,:] and the
// reciprocal clamped row norm. 8 warps/block, 4 rows/warp -> 32 rows/block.
// ---------------------------------------------------------------------------
__global__ void __launch_bounds__(256) k1_dots(const float* __restrict__ mem,
                                               const float* __restrict__ kq) {
    __shared__ float ks[HH * MM];  // 512 floats: k[b,:,:]
    const int blocks_per_b = SS / 32;
    const int b  = blockIdx.x / blocks_per_b;
    const int s0 = (blockIdx.x % blocks_per_b) * 32;

    for (int i = threadIdx.x; i < HH * MM; i += blockDim.x)
        ks[i] = kq[b * HH * MM + i];
    __syncthreads();

    const int warp = threadIdx.x >> 5;
    const int lane = threadIdx.x & 31;

    float4 kk[HH];
#pragma unroll
    for (int h = 0; h < HH; ++h)
        kk[h] = ((const float4*)(ks + h * MM))[lane];

#pragma unroll
    for (int r = 0; r < 4; ++r) {
        const int s = s0 + warp * 4 + r;
        const float4 v = ((const float4*)(mem + (size_t)(b * SS + s) * MM))[lane];

        float ss = v.x * v.x + v.y * v.y + v.z * v.z + v.w * v.w;
        float d[HH];
#pragma unroll
        for (int h = 0; h < HH; ++h)
            d[h] = v.x * kk[h].x + v.y * kk[h].y + v.z * kk[h].z + v.w * kk[h].w;

#pragma unroll
        for (int o = 16; o > 0; o >>= 1) {
            ss += __shfl_xor_sync(0xFFFFFFFFu, ss, o);
#pragma unroll
            for (int h = 0; h < HH; ++h)
                d[h] += __shfl_xor_sync(0xFFFFFFFFu, d[h], o);
        }
        if (lane == 0) {
            const float nrm = fmaxf(sqrtf(ss), 1e-8f);
            g_rmn[b * SS + s] = 1.0f / nrm;
#pragma unroll
            for (int h = 0; h < HH; ++h)
                g_w[(b * HH + h) * SS + s] = d[h];
        }
    }
}

// ---------------------------------------------------------------------------
// Kernel 2: per (b,h): knorm, logits = beta/knorm * dot * rmn, softmax over S.
// Also zero-initializes out[b,h,:] (poisoned by harness; kernel 3 atomics in).
// ---------------------------------------------------------------------------
__global__ void __launch_bounds__(256) k2_softmax(const float* __restrict__ kq,
                                                  const float* __restrict__ beta,
                                                  float* __restrict__ out) {
    const int bh = blockIdx.x;           // 0..127
    const int b  = bh / HH;
    __shared__ float red[256];
    __shared__ float s_scale;

    // knorm via warp 0
    if (threadIdx.x < 32) {
        const float4 kk = ((const float4*)(kq + bh * MM))[threadIdx.x];
        float ss = kk.x * kk.x + kk.y * kk.y + kk.z * kk.z + kk.w * kk.w;
#pragma unroll
        for (int o = 16; o > 0; o >>= 1)
            ss += __shfl_xor_sync(0xFFFFFFFFu, ss, o);
        if (threadIdx.x == 0) {
            const float kn = fmaxf(sqrtf(ss), 1e-8f);
            s_scale = beta[bh] / kn;
        }
    }
    if (threadIdx.x < MM)
        out[bh * MM + threadIdx.x] = 0.0f;
    __syncthreads();

    const float scale = s_scale;
    const int tid = threadIdx.x;
    float lg[SS / 256];  // 16
    float mx = -1e30f;
#pragma unroll
    for (int i = 0; i < SS / 256; ++i) {
        const int s = tid + i * 256;
        const float l = scale * g_w[bh * SS + s] * g_rmn[b * SS + s];
        lg[i] = l;
        mx = fmaxf(mx, l);
    }
    // block max
    red[tid] = mx; __syncthreads();
    for (int o = 128; o > 0; o >>= 1) {
        if (tid < o) red[tid] = fmaxf(red[tid], red[tid + o]);
        __syncthreads();
    }
    mx = red[0];
    __syncthreads();

    float sum = 0.0f;
#pragma unroll
    for (int i = 0; i < SS / 256; ++i) {
        const float e = __expf(lg[i] - mx);
        lg[i] = e;
        sum += e;
    }
    red[tid] = sum; __syncthreads();
    for (int o = 128; o > 0; o >>= 1) {
        if (tid < o) red[tid] += red[tid + o];
        __syncthreads();
    }
    const float inv = 1.0f / red[0];
#pragma unroll
    for (int i = 0; i < SS / 256; ++i)
        g_w[bh * SS + tid + i * 256] = lg[i] * inv;
}

// ---------------------------------------------------------------------------
// Kernel 3: fused write + read. Per memory element, apply 4 sequential
// erase/add head updates in registers, then accumulate w_h * nmem into
// per-thread accumulators -> shared -> global atomics.
// Grid: (NCHUNK, B). 256 threads; each warp streams rows (8-row stride).
// ---------------------------------------------------------------------------
#define NCHUNK 16
#define ROWS_PER_CHUNK (SS / NCHUNK)   // 256

__global__ void __launch_bounds__(256) k3_write_read(const float* __restrict__ mem,
                                                     const float* __restrict__ erase,
                                                     const float* __restrict__ add,
                                                     float* __restrict__ out) {
    const int b  = blockIdx.y;
    const int s0 = blockIdx.x * ROWS_PER_CHUNK;
    const int warp = threadIdx.x >> 5;
    const int lane = threadIdx.x & 31;

    __shared__ float acc[HH * MM];  // 512
    for (int i = threadIdx.x; i < HH * MM; i += blockDim.x)
        acc[i] = 0.0f;

    // erase/add into registers (lane owns columns lane*4 .. lane*4+3)
    float er[HH][4], ar[HH][4];
#pragma unroll
    for (int h = 0; h < HH; ++h) {
        const float4 e4 = __ldg((const float4*)(erase + (b * HH + h) * MM) + lane);
        const float4 a4 = __ldg((const float4*)(add   + (b * HH + h) * MM) + lane);
        er[h][0] = e4.x; er[h][1] = e4.y; er[h][2] = e4.z; er[h][3] = e4.w;
        ar[h][0] = a4.x; ar[h][1] = a4.y; ar[h][2] = a4.z; ar[h][3] = a4.w;
    }
    __syncthreads();

    float racc[HH][4];
#pragma unroll
    for (int h = 0; h < HH; ++h)
#pragma unroll
        for (int j = 0; j < 4; ++j) racc[h][j] = 0.0f;

    const int iters = ROWS_PER_CHUNK / 8;  // 32
    for (int it = 0; it < iters; ++it) {
        const int s = s0 + it * 8 + warp;
        const float4 v = ((const float4*)(mem + (size_t)(b * SS + s) * MM))[lane];
        float wh[HH];
#pragma unroll
        for (int h = 0; h < HH; ++h)
            wh[h] = __ldg(&g_w[(b * HH + h) * SS + s]);

        float vv[4] = {v.x, v.y, v.z, v.w};
#pragma unroll
        for (int j = 0; j < 4; ++j) {
            float x = vv[j];
#pragma unroll
            for (int h = 0; h < HH; ++h) {
                const float t = fmaf(-wh[h], er[h][j], 1.0f);  // 1 - w*e
                x = fmaf(x, t, wh[h] * ar[h][j]);              // x*(1-we) + w*a
            }
#pragma unroll
            for (int h = 0; h < HH; ++h)
                racc[h][j] = fmaf(wh[h], x, racc[h][j]);
        }
    }

#pragma unroll
    for (int h = 0; h < HH; ++h)
#pragma unroll
        for (int j = 0; j < 4; ++j)
            atomicAdd(&acc[h * MM + lane * 4 + j], racc[h][j]);
    __syncthreads();

    for (int i = threadIdx.x; i < HH * MM; i += blockDim.x)
        atomicAdd(&out[b * HH * MM + i], acc[i]);
}

// ---------------------------------------------------------------------------
extern "C" void kernel_launch(void* const* d_in, const int* in_sizes, int n_in,
                              void* d_out, int out_size) {
    const float* mem   = (const float*)d_in[0];  // (B,S,M)
    const float* kq    = (const float*)d_in[1];  // (B,H,M)
    const float* beta  = (const float*)d_in[2];  // (B,H,1)
    const float* erase = (const float*)d_in[3];  // (B,H,M)
    const float* add   = (const float*)d_in[4];  // (B,H,M)
    float* out = (float*)d_out;                  // (B,H,M)

    (void)in_sizes; (void)n_in; (void)out_size;

    k1_dots<<<BB * (SS / 32), 256>>>(mem, kq);
    k2_softmax<<<BB * HH, 256>>>(kq, beta, out);
    k3_write_read<<<dim3(NCHUNK, BB), 256>>>(mem, erase, add, out);
}

// round 2
// speedup vs baseline: 1.1660x; 1.1660x over previous
#include <cuda_runtime.h>
#include <cuda_bf16.h>

#define BB 32
#define HH 4
#define SS 4096
#define MM 128

typedef unsigned long long u64;

__device__ __forceinline__ u64 pack2(float lo, float hi) {
    u64 r; asm("mov.b64 %0,{%1,%2};" : "=l"(r) : "f"(lo), "f"(hi)); return r;
}
__device__ __forceinline__ float2 unpack2(u64 x) {
    float2 f; asm("mov.b64 {%0,%1},%2;" : "=f"(f.x), "=f"(f.y) : "l"(x)); return f;
}
__device__ __forceinline__ u64 fma2(u64 a, u64 b, u64 c) {
    u64 d; asm("fma.rn.f32x2 %0,%1,%2,%3;" : "=l"(d) : "l"(a), "l"(b), "l"(c)); return d;
}
__device__ __forceinline__ u64 mul2(u64 a, u64 b) {
    u64 d; asm("mul.rn.f32x2 %0,%1,%2;" : "=l"(d) : "l"(a), "l"(b)); return d;
}

// Scratch (allocation-free rule: __device__ globals)
__device__ float g_w[BB * HH * SS];   // dots*rmn, then softmax weights in-place

// ---------------------------------------------------------------------------
// Kernel 1: shared-staged, one thread per memory row, zero shuffles.
// Stores w[b,h,s] = dot(k_h, mem_s) / max(||mem_s||, eps)   (rmn folded in)
// ---------------------------------------------------------------------------
#define T1 128          // rows per tile == threads per block
#define K1S 132         // padded row stride in floats (16B-aligned, LDS.128 conflict-free)

__global__ void __launch_bounds__(T1) k1_dots(const float* __restrict__ mem,
                                              const float* __restrict__ kq) {
    extern __shared__ float sh[];            // [T1*K1S] stage + [HH*K1S] k
    float* stage = sh;
    float* ksh = sh + T1 * K1S;

    const int tiles_per_b = SS / T1;         // 32
    const int b  = blockIdx.x / tiles_per_b;
    const int s0 = (blockIdx.x % tiles_per_b) * T1;
    const int tid = threadIdx.x;

    // k into shared (broadcast-read later)
    for (int i = tid; i < HH * MM; i += T1)
        ksh[(i >> 7) * K1S + (i & 127)] = kq[b * HH * MM + i];

    // coalesced stage of 128 rows
    const float4* gsrc = (const float4*)(mem + ((size_t)b * SS + s0) * MM);
#pragma unroll
    for (int j = 0; j < 32; ++j) {
        const int l = tid + j * T1;          // 0..4095
        const int r = l >> 5, c = l & 31;
        const float4 v = gsrc[l];
        *(float4*)&stage[r * K1S + c * 4] = v;
    }
    __syncthreads();

    // each thread reduces its own row; packed f32x2 FMAs
    const ulonglong2* rowp = (const ulonglong2*)(stage + tid * K1S);
    u64 ss2 = 0, d2[HH] = {0, 0, 0, 0};
#pragma unroll 8
    for (int i = 0; i < 32; ++i) {
        const ulonglong2 v = rowp[i];
        ss2 = fma2(v.x, v.x, ss2);
        ss2 = fma2(v.y, v.y, ss2);
#pragma unroll
        for (int h = 0; h < HH; ++h) {
            const ulonglong2 kk = ((const ulonglong2*)(ksh + h * K1S))[i];  // broadcast
            d2[h] = fma2(v.x, kk.x, d2[h]);
            d2[h] = fma2(v.y, kk.y, d2[h]);
        }
    }
    const float2 sp = unpack2(ss2);
    const float rmn = 1.0f / fmaxf(sqrtf(sp.x + sp.y), 1e-8f);
    const int s = s0 + tid;
#pragma unroll
    for (int h = 0; h < HH; ++h) {
        const float2 dp = unpack2(d2[h]);
        g_w[(b * HH + h) * SS + s] = (dp.x + dp.y) * rmn;
    }
}

// ---------------------------------------------------------------------------
// Kernel 2: per (b,h): logits = (beta/knorm) * w, softmax over S. Zeroes out.
// ---------------------------------------------------------------------------
__global__ void __launch_bounds__(256) k2_softmax(const float* __restrict__ kq,
                                                  const float* __restrict__ beta,
                                                  float* __restrict__ out) {
    const int bh = blockIdx.x;               // 0..127
    __shared__ float red[256];
    __shared__ float s_scale;

    if (threadIdx.x < 32) {
        const float4 kk = ((const float4*)(kq + bh * MM))[threadIdx.x];
        float ss = kk.x * kk.x + kk.y * kk.y + kk.z * kk.z + kk.w * kk.w;
#pragma unroll
        for (int o = 16; o > 0; o >>= 1)
            ss += __shfl_xor_sync(0xFFFFFFFFu, ss, o);
        if (threadIdx.x == 0)
            s_scale = beta[bh] / fmaxf(sqrtf(ss), 1e-8f);
    }
    if (threadIdx.x < MM)
        out[bh * MM + threadIdx.x] = 0.0f;
    __syncthreads();

    const float scale = s_scale;
    const int tid = threadIdx.x;
    float lg[SS / 256];
    float mx = -1e30f;
#pragma unroll
    for (int i = 0; i < SS / 256; ++i) {
        const float l = scale * g_w[bh * SS + tid + i * 256];
        lg[i] = l;
        mx = fmaxf(mx, l);
    }
    red[tid] = mx; __syncthreads();
    for (int o = 128; o > 0; o >>= 1) {
        if (tid < o) red[tid] = fmaxf(red[tid], red[tid + o]);
        __syncthreads();
    }
    mx = red[0];
    __syncthreads();

    float sum = 0.0f;
#pragma unroll
    for (int i = 0; i < SS / 256; ++i) {
        const float e = __expf(lg[i] - mx);
        lg[i] = e;
        sum += e;
    }
    red[tid] = sum; __syncthreads();
    for (int o = 128; o > 0; o >>= 1) {
        if (tid < o) red[tid] += red[tid + o];
        __syncthreads();
    }
    const float inv = 1.0f / red[0];
#pragma unroll
    for (int i = 0; i < SS / 256; ++i)
        g_w[bh * SS + tid + i * 256] = lg[i] * inv;
}

// ---------------------------------------------------------------------------
// Kernel 3: fused write + read, packed f32x2 inner math.
// ---------------------------------------------------------------------------
#define NCHUNK 16
#define ROWS_PER_CHUNK (SS / NCHUNK)   // 256

__global__ void __launch_bounds__(256) k3_write_read(const float* __restrict__ mem,
                                                     const float* __restrict__ erase,
                                                     const float* __restrict__ add,
                                                     float* __restrict__ out) {
    const int b  = blockIdx.y;
    const int s0 = blockIdx.x * ROWS_PER_CHUNK;
    const int warp = threadIdx.x >> 5;
    const int lane = threadIdx.x & 31;

    __shared__ float acc[HH * MM];
    for (int i = threadIdx.x; i < HH * MM; i += blockDim.x)
        acc[i] = 0.0f;

    // packed per-lane erase(-negated)/add pairs (lane owns cols lane*4..+3)
    u64 ner2[HH][2], ar2[HH][2];
#pragma unroll
    for (int h = 0; h < HH; ++h) {
        const float4 e4 = __ldg((const float4*)(erase + (b * HH + h) * MM) + lane);
        const float4 a4 = __ldg((const float4*)(add   + (b * HH + h) * MM) + lane);
        ner2[h][0] = pack2(-e4.x, -e4.y);
        ner2[h][1] = pack2(-e4.z, -e4.w);
        ar2[h][0]  = pack2(a4.x, a4.y);
        ar2[h][1]  = pack2(a4.z, a4.w);
    }
    const u64 ones = pack2(1.0f, 1.0f);
    __syncthreads();

    u64 racc[HH][2];
#pragma unroll
    for (int h = 0; h < HH; ++h) { racc[h][0] = 0; racc[h][1] = 0; }

    const int iters = ROWS_PER_CHUNK / 8;  // 32
    for (int it = 0; it < iters; ++it) {
        const int s = s0 + it * 8 + warp;
        const ulonglong2 v = ((const ulonglong2*)(mem + ((size_t)b * SS + s) * MM))[lane];
        u64 w2[HH];
#pragma unroll
        for (int h = 0; h < HH; ++h) {
            const float wh = __ldg(&g_w[(b * HH + h) * SS + s]);
            w2[h] = pack2(wh, wh);
        }
        u64 x0 = v.x, x1 = v.y;
#pragma unroll
        for (int h = 0; h < HH; ++h) {
            const u64 t0  = fma2(ner2[h][0], w2[h], ones);   // 1 - w*e
            const u64 t1  = fma2(ner2[h][1], w2[h], ones);
            const u64 wa0 = mul2(w2[h], ar2[h][0]);          // w*a
            const u64 wa1 = mul2(w2[h], ar2[h][1]);
            x0 = fma2(x0, t0, wa0);
            x1 = fma2(x1, t1, wa1);
        }
#pragma unroll
        for (int h = 0; h < HH; ++h) {
            racc[h][0] = fma2(w2[h], x0, racc[h][0]);
            racc[h][1] = fma2(w2[h], x1, racc[h][1]);
        }
    }

#pragma unroll
    for (int h = 0; h < HH; ++h) {
        const float2 r0 = unpack2(racc[h][0]);
        const float2 r1 = unpack2(racc[h][1]);
        atomicAdd(&acc[h * MM + lane * 4 + 0], r0.x);
        atomicAdd(&acc[h * MM + lane * 4 + 1], r0.y);
        atomicAdd(&acc[h * MM + lane * 4 + 2], r1.x);
        atomicAdd(&acc[h * MM + lane * 4 + 3], r1.y);
    }
    __syncthreads();

    for (int i = threadIdx.x; i < HH * MM; i += blockDim.x)
        atomicAdd(&out[b * HH * MM + i], acc[i]);
}

// ---------------------------------------------------------------------------
extern "C" void kernel_launch(void* const* d_in, const int* in_sizes, int n_in,
                              void* d_out, int out_size) {
    const float* mem   = (const float*)d_in[0];  // (B,S,M)
    const float* kq    = (const float*)d_in[1];  // (B,H,M)
    const float* beta  = (const float*)d_in[2];  // (B,H,1)
    const float* erase = (const float*)d_in[3];  // (B,H,M)
    const float* add   = (const float*)d_in[4];  // (B,H,M)
    float* out = (float*)d_out;                  // (B,H,M)

    (void)in_sizes; (void)n_in; (void)out_size;

    const int smem1 = (T1 * K1S + HH * K1S) * sizeof(float);   // ~69.7 KB
    cudaFuncSetAttribute(k1_dots, cudaFuncAttributeMaxDynamicSharedMemorySize, smem1);

    k1_dots<<<BB * (SS / T1), T1, smem1>>>(mem, kq);
    k2_softmax<<<BB * HH, 256>>>(kq, beta, out);
    k3_write_read<<<dim3(NCHUNK, BB), 256>>>(mem, erase, add, out);
}

// round 4
// speedup vs baseline: 1.2129x; 1.0402x over previous
#include <cuda_runtime.h>
#include <cuda_bf16.h>

#define BB 32
#define HH 4
#define SS 4096
#define MM 128

typedef unsigned long long u64;

__device__ __forceinline__ u64 fma2(u64 a, u64 b, u64 c) {
    u64 d; asm("fma.rn.f32x2 %0,%1,%2,%3;" : "=l"(d) : "l"(a), "l"(b), "l"(c)); return d;
}
__device__ __forceinline__ u64 mul2(u64 a, u64 b) {
    u64 d; asm("mul.rn.f32x2 %0,%1,%2;" : "=l"(d) : "l"(a), "l"(b)); return d;
}
__device__ __forceinline__ u64 pack2(float lo, float hi) {
    u64 r; asm("mov.b64 %0,{%1,%2};" : "=l"(r) : "f"(lo), "f"(hi)); return r;
}
__device__ __forceinline__ float2 unpack2(u64 x) {
    float2 f; asm("mov.b64 {%0,%1},%2;" : "=f"(f.x), "=f"(f.y) : "l"(x)); return f;
}
__device__ __forceinline__ float hadd2(u64 x) {
    const float2 f = unpack2(x); return f.x + f.y;
}

// Scratch: w stored transposed [b][s][h] as float4 per row
__device__ float4 g_w[BB * SS];

// ---------------------------------------------------------------------------
// Kernel 1: 8 lanes per row, 4 rows per warp-quad, k in registers,
// 3-stage shuffle reduction, depth-1 prefetch.
// Stores g_w[b*SS+s] = {dot_h(k_h, mem_s) * rmn_s} for h=0..3 (rmn folded).
// ---------------------------------------------------------------------------
__global__ void __launch_bounds__(256, 2) k1_dots(const float* __restrict__ mem,
                                                  const float* __restrict__ kq) {
    const int b    = blockIdx.x >> 5;        // 32 tiles per b
    const int tile = blockIdx.x & 31;        // 128 rows per tile
    const int warp = threadIdx.x >> 5;
    const int lane = threadIdx.x & 31;
    const int l8   = lane & 7;
    const int r    = lane >> 3;

    // k into registers: per lane, 4 heads x 4 float4 (cols j*32 + l8*4)
    ulonglong2 kk[HH][4];
#pragma unroll
    for (int h = 0; h < HH; ++h)
#pragma unroll
        for (int j = 0; j < 4; ++j)
            kk[h][j] = *(const ulonglong2*)(kq + ((b * HH + h) << 7) + j * 32 + l8 * 4);

    // row for quad q: s = tile*128 + q*32 + warp*4 + r
    const int srow0 = tile * 128 + warp * 4 + r;
    const float* base = mem + ((size_t)b * SS + srow0) * MM + l8 * 4;

    ulonglong2 vn[4];
#pragma unroll
    for (int j = 0; j < 4; ++j)
        vn[j] = *(const ulonglong2*)(base + j * 32);

#pragma unroll
    for (int q = 0; q < 4; ++q) {
        ulonglong2 vc[4];
#pragma unroll
        for (int j = 0; j < 4; ++j) vc[j] = vn[j];
        if (q < 3) {
            const float* nb = base + (size_t)(q + 1) * 32 * MM;
#pragma unroll
            for (int j = 0; j < 4; ++j)
                vn[j] = *(const ulonglong2*)(nb + j * 32);
        }

        u64 ss2 = 0, d2[HH] = {0, 0, 0, 0};
#pragma unroll
        for (int j = 0; j < 4; ++j) {
            ss2 = fma2(vc[j].x, vc[j].x, ss2);
            ss2 = fma2(vc[j].y, vc[j].y, ss2);
#pragma unroll
            for (int h = 0; h < HH; ++h) {
                d2[h] = fma2(vc[j].x, kk[h][j].x, d2[h]);
                d2[h] = fma2(vc[j].y, kk[h][j].y, d2[h]);
            }
        }

        float ssum = hadd2(ss2);
        float sd[HH];
#pragma unroll
        for (int h = 0; h < HH; ++h) sd[h] = hadd2(d2[h]);

#pragma unroll
        for (int o = 4; o > 0; o >>= 1) {
            ssum += __shfl_xor_sync(0xFFFFFFFFu, ssum, o);
#pragma unroll
            for (int h = 0; h < HH; ++h)
                sd[h] += __shfl_xor_sync(0xFFFFFFFFu, sd[h], o);
        }

        if (l8 == 0) {
            const float rmn = 1.0f / fmaxf(sqrtf(ssum), 1e-8f);
            const int s = srow0 + q * 32;
            g_w[b * SS + s] = make_float4(sd[0] * rmn, sd[1] * rmn,
                                          sd[2] * rmn, sd[3] * rmn);
        }
    }
}

// ---------------------------------------------------------------------------
// Kernel 2: per-b block. Softmax over S for all 4 heads at once (float4).
// Also zero-initializes out[b,:,:].
// ---------------------------------------------------------------------------
__global__ void __launch_bounds__(256) k2_softmax(const float* __restrict__ kq,
                                                  const float* __restrict__ beta,
                                                  float* __restrict__ out) {
    const int b = blockIdx.x;
    const int tid = threadIdx.x;
    const int wid = tid >> 5, lane = tid & 31;

    __shared__ float scl[HH];
    __shared__ float4 red[256];

    if (wid < HH) {
        const float4 kv = ((const float4*)(kq + (b * HH + wid) * MM))[lane];
        float ss = kv.x * kv.x + kv.y * kv.y + kv.z * kv.z + kv.w * kv.w;
#pragma unroll
        for (int o = 16; o > 0; o >>= 1)
            ss += __shfl_xor_sync(0xFFFFFFFFu, ss, o);
        if (lane == 0)
            scl[wid] = beta[b * HH + wid] / fmaxf(sqrtf(ss), 1e-8f);
    }
    out[b * HH * MM + tid] = 0.0f;
    out[b * HH * MM + 256 + tid] = 0.0f;
    __syncthreads();

    const float4 sc = make_float4(scl[0], scl[1], scl[2], scl[3]);

    float4 lg[SS / 256];  // 16
    float4 mx = make_float4(-1e30f, -1e30f, -1e30f, -1e30f);
#pragma unroll
    for (int i = 0; i < SS / 256; ++i) {
        float4 v = g_w[b * SS + tid + i * 256];
        v.x *= sc.x; v.y *= sc.y; v.z *= sc.z; v.w *= sc.w;
        lg[i] = v;
        mx.x = fmaxf(mx.x, v.x); mx.y = fmaxf(mx.y, v.y);
        mx.z = fmaxf(mx.z, v.z); mx.w = fmaxf(mx.w, v.w);
    }
    red[tid] = mx; __syncthreads();
    for (int o = 128; o > 0; o >>= 1) {
        if (tid < o) {
            float4 a = red[tid], c = red[tid + o];
            red[tid] = make_float4(fmaxf(a.x, c.x), fmaxf(a.y, c.y),
                                   fmaxf(a.z, c.z), fmaxf(a.w, c.w));
        }
        __syncthreads();
    }
    mx = red[0];
    __syncthreads();

    float4 sum = make_float4(0, 0, 0, 0);
#pragma unroll
    for (int i = 0; i < SS / 256; ++i) {
        float4 v = lg[i];
        v.x = __expf(v.x - mx.x); v.y = __expf(v.y - mx.y);
        v.z = __expf(v.z - mx.z); v.w = __expf(v.w - mx.w);
        lg[i] = v;
        sum.x += v.x; sum.y += v.y; sum.z += v.z; sum.w += v.w;
    }
    red[tid] = sum; __syncthreads();
    for (int o = 128; o > 0; o >>= 1) {
        if (tid < o) {
            float4 a = red[tid], c = red[tid + o];
            red[tid] = make_float4(a.x + c.x, a.y + c.y, a.z + c.z, a.w + c.w);
        }
        __syncthreads();
    }
    const float4 tot = red[0];
    const float4 inv = make_float4(1.0f / tot.x, 1.0f / tot.y,
                                   1.0f / tot.z, 1.0f / tot.w);
#pragma unroll
    for (int i = 0; i < SS / 256; ++i) {
        float4 v = lg[i];
        v.x *= inv.x; v.y *= inv.y; v.z *= inv.z; v.w *= inv.w;
        g_w[b * SS + tid + i * 256] = v;
    }
}

// ---------------------------------------------------------------------------
// Kernel 3: fused write + read, packed f32x2, float4 broadcast w load.
// ---------------------------------------------------------------------------
#define NCHUNK 32
#define ROWS_PER_CHUNK (SS / NCHUNK)   // 128

__global__ void __launch_bounds__(256) k3_write_read(const float* __restrict__ mem,
                                                     const float* __restrict__ erase,
                                                     const float* __restrict__ add,
                                                     float* __restrict__ out) {
    const int b  = blockIdx.y;
    const int s0 = blockIdx.x * ROWS_PER_CHUNK;
    const int warp = threadIdx.x >> 5;
    const int lane = threadIdx.x & 31;

    __shared__ float acc[HH * MM];
    for (int i = threadIdx.x; i < HH * MM; i += blockDim.x)
        acc[i] = 0.0f;

    u64 ner2[HH][2], ar2[HH][2];
#pragma unroll
    for (int h = 0; h < HH; ++h) {
        const float4 e4 = __ldg((const float4*)(erase + (b * HH + h) * MM) + lane);
        const float4 a4 = __ldg((const float4*)(add   + (b * HH + h) * MM) + lane);
        ner2[h][0] = pack2(-e4.x, -e4.y);
        ner2[h][1] = pack2(-e4.z, -e4.w);
        ar2[h][0]  = pack2(a4.x, a4.y);
        ar2[h][1]  = pack2(a4.z, a4.w);
    }
    const u64 ones = pack2(1.0f, 1.0f);
    __syncthreads();

    u64 racc[HH][2];
#pragma unroll
    for (int h = 0; h < HH; ++h) { racc[h][0] = 0; racc[h][1] = 0; }

    const int iters = ROWS_PER_CHUNK / 8;  // 16
    for (int it = 0; it < iters; ++it) {
        const int s = s0 + it * 8 + warp;
        const ulonglong2 v = ((const ulonglong2*)(mem + ((size_t)b * SS + s) * MM))[lane];
        const float4 wq = __ldg(&g_w[b * SS + s]);   // broadcast, 1 line
        u64 w2[HH];
        w2[0] = pack2(wq.x, wq.x); w2[1] = pack2(wq.y, wq.y);
        w2[2] = pack2(wq.z, wq.z); w2[3] = pack2(wq.w, wq.w);

        u64 x0 = v.x, x1 = v.y;
#pragma unroll
        for (int h = 0; h < HH; ++h) {
            const u64 t0  = fma2(ner2[h][0], w2[h], ones);   // 1 - w*e
            const u64 t1  = fma2(ner2[h][1], w2[h], ones);
            const u64 wa0 = mul2(w2[h], ar2[h][0]);          // w*a
            const u64 wa1 = mul2(w2[h], ar2[h][1]);
            x0 = fma2(x0, t0, wa0);
            x1 = fma2(x1, t1, wa1);
        }
#pragma unroll
        for (int h = 0; h < HH; ++h) {
            racc[h][0] = fma2(w2[h], x0, racc[h][0]);
            racc[h][1] = fma2(w2[h], x1, racc[h][1]);
        }
    }

#pragma unroll
    for (int h = 0; h < HH; ++h) {
        const float2 r0 = unpack2(racc[h][0]);
        const float2 r1 = unpack2(racc[h][1]);
        atomicAdd(&acc[h * MM + lane * 4 + 0], r0.x);
        atomicAdd(&acc[h * MM + lane * 4 + 1], r0.y);
        atomicAdd(&acc[h * MM + lane * 4 + 2], r1.x);
        atomicAdd(&acc[h * MM + lane * 4 + 3], r1.y);
    }
    __syncthreads();

    for (int i = threadIdx.x; i < HH * MM; i += blockDim.x)
        atomicAdd(&out[b * HH * MM + i], acc[i]);
}

// ---------------------------------------------------------------------------
extern "C" void kernel_launch(void* const* d_in, const int* in_sizes, int n_in,
                              void* d_out, int out_size) {
    const float* mem   = (const float*)d_in[0];  // (B,S,M)
    const float* kq    = (const float*)d_in[1];  // (B,H,M)
    const float* beta  = (const float*)d_in[2];  // (B,H,1)
    const float* erase = (const float*)d_in[3];  // (B,H,M)
    const float* add   = (const float*)d_in[4];  // (B,H,M)
    float* out = (float*)d_out;                  // (B,H,M)

    (void)in_sizes; (void)n_in; (void)out_size;

    k1_dots<<<BB * 32, 256>>>(mem, kq);
    k2_softmax<<<BB, 256>>>(kq, beta, out);
    k3_write_read<<<dim3(NCHUNK, BB), 256>>>(mem, erase, add, out);
}